// round 14
// baseline (speedup 1.0000x reference)
#include <cuda_runtime.h>
#include <cuda_bf16.h>

// x: [3,5,32,64,32,32] binary float. Per 32x32 image (4-connectivity):
// result = max(#background, largest foreground component).
// Output[C,B,Bt] = (sum over 64 patches) // 64 as float. 480 outputs.
//
// Level-1 exact skip: fg <= 512 => largest <= fg <= bg => res = bg (no transpose).
// Level-2 exact skip: size<=2 isolated comps can't win; if 2*fg <= 1024+excl
// => res = bg (no CCL). CCL runs on ~3% of images.
//
// Persistent warps (592 blocks = 4/SM, fully resident), each grid-strides over
// ~13 images with next-image loads software-pipelined past current compute.

#define N_IMG 30720
#define N_OUT 480
#define NBLOCKS 592
#define WARPS_PER_BLK 4
#define STRIDE (NBLOCKS * WARPS_PER_BLK)   // 2368 warps

__device__ int g_acc[N_OUT];   // zero-init at load; last block resets after read
__device__ int g_cnt;          // completion ticket; reset each launch

__device__ __forceinline__ int uf_find(int* Lp, int i) {
    volatile int* L = Lp;
    int p = L[i];
    if (p == i) return i;
    while (true) {
        int gp = L[p];
        if (gp == p) return p;
        L[i] = gp;          // path halving (always stores a valid ancestor)
        i = p; p = gp;
    }
}

__device__ __forceinline__ void uf_union(int* L, int a, int b) {
    while (true) {
        a = uf_find(L, a);
        b = uf_find(L, b);
        if (a == b) return;
        int mn = min(a, b);
        int mx = max(a, b);
        int old = atomicMin(&L[mx], mn);
        if (old == mx) return;
        a = old; b = mn;
    }
}

__device__ __forceinline__ int lane_of_row(int t) {   // inverse of r = 4*(l&7)+(l>>3)
    return ((t & 3) << 3) + (t >> 2);
}

__device__ __forceinline__ void load_img(const float4* __restrict__ x, int img,
                                         int lane, float4 v[8]) {
    const float4* p = x + (size_t)img * 256 + lane;
#pragma unroll
    for (int i = 0; i < 8; i++) v[i] = __ldcs(p + i * 32);   // 512B contiguous, MLP=8
}

__device__ __forceinline__ int process(const float4 v[8], int lane, int* L) {
    // ---- pack 8 nibbles; values are exactly 0.0/1.0 so x+2y+4z+8w is exact ----
    unsigned m = 0;
#pragma unroll
    for (int i = 0; i < 8; i++) {
        float f = fmaf(8.0f, v[i].w, fmaf(4.0f, v[i].z, fmaf(2.0f, v[i].y, v[i].x)));
        m |= ((unsigned)(int)f) << (4 * i);
    }
    // lane l, nibble i = (row 4i + (l>>3), cols 4*(l&7)..4*(l&7)+3)

    const int fg = __reduce_add_sync(~0u, __popc(m));   // layout-independent
    int res = 1024 - fg;                                // background count
    if (fg <= 512) return res;                          // level-1 skip (~50%)

    // ---- 8x8 nibble transpose within each 8-lane group (3 butterfly steps) ----
    {
        unsigned y;
        y = __shfl_xor_sync(~0u, m, 4);
        m = (lane & 4) ? ((m & 0xFFFF0000u) | (y >> 16))
                       : ((m & 0x0000FFFFu) | (y << 16));
        y = __shfl_xor_sync(~0u, m, 2);
        m = (lane & 2) ? ((m & 0xFF00FF00u) | ((y >> 8) & 0x00FF00FFu))
                       : ((m & 0x00FF00FFu) | ((y << 8) & 0xFF00FF00u));
        y = __shfl_xor_sync(~0u, m, 1);
        m = (lane & 1) ? ((m & 0xF0F0F0F0u) | ((y >> 4) & 0x0F0F0F0Fu))
                       : ((m & 0x0F0F0F0Fu) | ((y << 4) & 0xF0F0F0F0u));
    }
    const int r = 4 * (lane & 7) + (lane >> 3);          // row held by this lane

    // ---- neighbor row masks (0 at image boundary) ----
    unsigned up  = __shfl_sync(~0u, m, lane_of_row((r - 1) & 31));
    unsigned dn  = __shfl_sync(~0u, m, lane_of_row((r + 1) & 31));
    unsigned dn2 = __shfl_sync(~0u, m, lane_of_row((r + 2) & 31));
    if (r == 0)   up  = 0;
    if (r == 31)  dn  = 0;
    if (r >= 30)  dn2 = 0;

    // ---- size<=2 isolated components (exact) ----
    unsigned iso = m & ~(m << 1) & ~(m >> 1) & ~up & ~dn;
    unsigned hd  = m & (m >> 1) & ~(m << 1) & ~(m >> 2)
                 & ~up & ~(up >> 1) & ~dn & ~(dn >> 1);   // horiz domino
    unsigned vd  = m & dn & ~up & ~dn2
                 & ~(m << 1) & ~(m >> 1) & ~(dn << 1) & ~(dn >> 1); // vert domino
    const int excl = __reduce_add_sync(
        ~0u, __popc(iso) + 2 * (__popc(hd) + __popc(vd)));

    if (2 * fg <= 1024 + excl) return res;               // level-2 skip

    // ---- run-based union-find (~3% of images) ----
    const unsigned s = m & ~(m << 1);                    // run-start bits
    const int nr = __popc(s);

    for (int k = 0; k < nr; k++)                         // node id = k*32 + r
        L[k * 32 + r] = k * 32 + r;
    __syncwarp();

    unsigned s_d = __shfl_sync(~0u, s, lane_of_row((r + 1) & 31));
    if (r < 31) {
        unsigned ov = m & dn;
        unsigned st = ov & ~(ov << 1);
        while (st) {
            int c = __ffs(st) - 1;
            st &= st - 1;
            unsigned thr = (2u << c) - 1u;               // bits 0..c
            int kr = __popc(s   & thr) - 1;              // run idx in row r
            int kd = __popc(s_d & thr) - 1;              // run idx in row r+1
            uf_union(L, kr * 32 + r, kd * 32 + r + 1);
        }
    }
    __syncwarp();

    // phase A: fully flatten every run to its root
    for (int k = 0; k < nr; k++) {
        int id = k * 32 + r;
        int rt = uf_find(L, id);
        if (rt != id) L[id] = rt;
    }
    __syncwarp();

    // phase B: run lengths into bits >=10 of L[root]; mask low 10 bits when
    // reading root (adds only touch bits >=10, root idx < 512) -> race-safe
    {
        unsigned st = s;
        int k = 0;
        while (st) {
            int c = __ffs(st) - 1;
            st &= st - 1;
            unsigned inv = ~(m >> c);
            int len = inv ? (__ffs(inv) - 1) : 32;       // trailing-ones of m>>c
            int root = L[k * 32 + r] & 1023;
            atomicAdd(&L[root], len << 10);
            k++;
        }
    }
    __syncwarp();

    int mymax = 0;
    for (int k = 0; k < nr; k++)
        mymax = max(mymax, L[k * 32 + r] >> 10);         // non-roots -> 0
    mymax = __reduce_max_sync(~0u, mymax);
    return max(mymax, res);
}

__global__ void __launch_bounds__(128, 4)
ccl_kernel(const float4* __restrict__ x, float* __restrict__ out) {
    __shared__ int Ls[WARPS_PER_BLK][512];
    __shared__ int s_last;

    const int lane = threadIdx.x & 31;
    const int w    = threadIdx.x >> 5;
    int* L = Ls[w];

    int img = blockIdx.x * WARPS_PER_BLK + w;            // < 2368 < N_IMG
    float4 v[8];
    load_img(x, img, lane, v);

    while (true) {
        const int nimg = img + STRIDE;
        const bool more = (nimg < N_IMG);                // warp-uniform
        float4 vn[8];
        if (more) load_img(x, nimg, lane, vn);           // pipelined past process()

        int res = process(v, lane, L);
        if (lane == 0)
            atomicAdd(&g_acc[img >> 6], res);            // 64 patches per cell

        if (!more) break;
#pragma unroll
        for (int i = 0; i < 8; i++) v[i] = vn[i];
        img = nimg;
    }

    // ---- last-block-done: fused finalize ----
    __syncthreads();
    if (threadIdx.x == 0) {
        __threadfence();
        int old = atomicAdd(&g_cnt, 1);
        s_last = (old == NBLOCKS - 1);
    }
    __syncthreads();
    if (s_last) {
        __threadfence();
        for (int i = threadIdx.x; i < N_OUT; i += blockDim.x) {
            int vv = __ldcg(&g_acc[i]);
            out[i] = (float)(vv >> 6);                   // truncating integer mean
            __stcg(&g_acc[i], 0);                        // reset for next replay
        }
        if (threadIdx.x == 0) __stcg(&g_cnt, 0);
    }
}

extern "C" void kernel_launch(void* const* d_in, const int* in_sizes, int n_in,
                              void* d_out, int out_size) {
    const float4* x = (const float4*)d_in[0];
    float* out = (float*)d_out;
    ccl_kernel<<<NBLOCKS, 128>>>(x, out);
}